// round 14
// baseline (speedup 1.0000x reference)
#include <cuda_runtime.h>
#include <cuda_fp16.h>
#include <cstdint>

// Problem constants
#define Bb    8
#define Nseq  4096
#define DIMc  1024
#define Hh    16
#define Mm    (Bb * Nseq)      // 32768 rows
#define NSPLIT 32

// ---------------- scratch (static device allocations only) ----------------
__device__ __align__(16) __half g_wh[(size_t)Mm * DIMc];   // w in fp16 (64MB)
__device__ __align__(16) __half g_xh[(size_t)Mm * DIMc];
__device__ __align__(16) __half g_yh[(size_t)Mm * DIMc];
__device__ __align__(16) __half g_W1h[DIMc * DIMc];
__device__ __align__(16) __half g_W2h[DIMc * DIMc];
__device__ float g_Pi[Mm * Hh];
__device__ float g_part1[NSPLIT * Bb * DIMc];
__device__ float g_part2[NSPLIT * Bb * DIMc];
__device__ float g_innorm[Bb * DIMc];
__device__ float g_Sp[(Mm / 8) * Hh];
__device__ float g_invS[Bb * Hh];
__device__ float g_attn[Bb * DIMc];
__device__ float g_dpart[(size_t)(Mm / 8) * DIMc];

// ============================ helpers ======================================
#define CP16(dst, src) \
    asm volatile("cp.async.cg.shared.global [%0], [%1], 16;" :: "r"(dst), "l"(src) : "memory")
#define CP_COMMIT() asm volatile("cp.async.commit_group;" ::: "memory")
#define CP_WAIT(n)  asm volatile("cp.async.wait_group %0;" :: "n"(n) : "memory")

__device__ __forceinline__ uint32_t smem_u32(const void* p) {
    uint32_t a;
    asm("{ .reg .u64 t; cvta.to.shared.u64 t, %1; cvt.u32.u64 %0, t; }"
        : "=r"(a) : "l"(p));
    return a;
}
#define LDSM4(r0, r1, r2, r3, addr) \
    asm volatile("ldmatrix.sync.aligned.m8n8.x4.shared.b16 {%0,%1,%2,%3}, [%4];" \
        : "=r"(r0), "=r"(r1), "=r"(r2), "=r"(r3) : "r"(addr))

__device__ __forceinline__ void mma_f16(float c[4], uint32_t a0, uint32_t a1,
                                        uint32_t a2, uint32_t a3,
                                        uint32_t b0, uint32_t b1) {
    asm volatile(
        "mma.sync.aligned.m16n8k16.row.col.f32.f16.f16.f32 "
        "{%0,%1,%2,%3}, {%4,%5,%6,%7}, {%8,%9}, {%0,%1,%2,%3};"
        : "+f"(c[0]), "+f"(c[1]), "+f"(c[2]), "+f"(c[3])
        : "r"(a0), "r"(a1), "r"(a2), "r"(a3), "r"(b0), "r"(b1));
}

// ======================= fp16 GEMM (mma.sync m16n8k16) =====================
// Block tile 128x128, 128 threads = 4 warps (2M x 2N), warp tile 64x64.
// K chunked by 32, 3-stage cp.async pipeline (61.4KB smem) so 3 CTAs/SM
// co-reside (3x61.4KB = 184KB, regs capped 168). SROWH=40: 80B row stride,
// 16B-aligned and bank-conflict-free.
#define KC      32
#define SROWH   40
#define AREG_B  (128 * SROWH * 2)           // 10240 bytes
#define STG_B   (2 * AREG_B)                // 20480 bytes per stage
#define NSTG    3
#define GSMEM   (NSTG * STG_B)              // 61440 bytes

template <typename OutT>
__global__ __launch_bounds__(128, 3)
void gemm_f16(const __half* __restrict__ A, const __half* __restrict__ W,
              OutT* __restrict__ C, const float* __restrict__ bias,
              float* __restrict__ sumsq) {
    extern __shared__ __half smemh[];
    const int tid = threadIdx.x, wid = tid >> 5, lane = tid & 31;
    const int bn = blockIdx.x, bm = blockIdx.y;
    const int wm = wid & 1, wn = wid >> 1;
    const int q  = lane >> 2, qc = lane & 3;
    const uint32_t smb = smem_u32(smemh);

    // reg-lean cp.async addressing: seg s covers row rA + s*32
    const int rA = tid >> 2, cseg = tid & 3;
    const __half* pA = A + (size_t)(bm * 128 + rA) * DIMc + cseg * 8;
    const __half* pB = W + (size_t)(bn * 128 + rA) * DIMc + cseg * 8;
    const uint32_t oA = (uint32_t)((rA * SROWH + cseg * 8) * 2);   // 16B aligned

    auto load_chunk = [&](int c) {
        uint32_t st = smb + (uint32_t)((c % 3) * STG_B);
        const __half* a = pA + c * KC;
        const __half* b = pB + c * KC;
#pragma unroll
        for (int s = 0; s < 4; s++)
            CP16(st + oA + s * (32 * SROWH * 2), a + (size_t)s * 32 * DIMc);
#pragma unroll
        for (int s = 0; s < 4; s++)
            CP16(st + AREG_B + oA + s * (32 * SROWH * 2), b + (size_t)s * 32 * DIMc);
        CP_COMMIT();
    };

    const int arow = (lane & 7) + 8 * ((lane >> 3) & 1);
    const int acol = 8 * (lane >> 4);
    const int brow = (lane & 7) + 8 * (lane >> 4);
    const int bcol = 8 * ((lane >> 3) & 1);

    float acc[4][8][4];
#pragma unroll
    for (int i = 0; i < 4; i++)
#pragma unroll
        for (int j = 0; j < 8; j++)
#pragma unroll
            for (int v = 0; v < 4; v++) acc[i][j][v] = 0.f;

    load_chunk(0); load_chunk(1);

    const int NCHUNK = DIMc / KC;        // 32
    for (int c = 0; c < NCHUNK; ++c) {
        CP_WAIT(1);                      // chunk c resident
        __syncthreads();                 // all threads done with stage (c-1)%3
        if (c + 2 < NCHUNK) load_chunk(c + 2);
        else CP_COMMIT();                // keep group count uniform

        uint32_t stA = smb + (uint32_t)((c % 3) * STG_B);
        uint32_t stB = stA + AREG_B;
#pragma unroll
        for (int ks = 0; ks < 2; ++ks) {
            const int k0 = ks * 16;
            uint32_t af[4][4], bf[8][2];
#pragma unroll
            for (int i = 0; i < 4; i++) {
                uint32_t ad = stA + (uint32_t)(((wm * 64 + i * 16 + arow) * SROWH
                                                + k0 + acol) * 2);
                LDSM4(af[i][0], af[i][1], af[i][2], af[i][3], ad);
            }
#pragma unroll
            for (int jp = 0; jp < 4; jp++) {
                uint32_t bd = stB + (uint32_t)(((wn * 64 + jp * 16 + brow) * SROWH
                                                + k0 + bcol) * 2);
                uint32_t t0, t1, t2, t3;
                LDSM4(t0, t1, t2, t3, bd);
                bf[jp * 2][0] = t0; bf[jp * 2][1] = t1;
                bf[jp * 2 + 1][0] = t2; bf[jp * 2 + 1][1] = t3;
            }
#pragma unroll
            for (int i = 0; i < 4; i++)
#pragma unroll
                for (int j = 0; j < 8; j++)
                    mma_f16(acc[i][j], af[i][0], af[i][1], af[i][2], af[i][3],
                            bf[j][0], bf[j][1]);
        }
    }

    // epilogue
#pragma unroll
    for (int j = 0; j < 8; j++) {
        int col = bn * 128 + wn * 64 + j * 8 + qc * 2;
        float b0 = 0.f, b1 = 0.f;
        if (bias) { b0 = bias[col]; b1 = bias[col + 1]; }
#pragma unroll
        for (int i = 0; i < 4; i++) {
            int row = bm * 128 + wm * 64 + i * 16 + q;
            if constexpr (sizeof(OutT) == 4) {
                float2 v0 = make_float2(acc[i][j][0] + b0, acc[i][j][1] + b1);
                float2 v1 = make_float2(acc[i][j][2] + b0, acc[i][j][3] + b1);
                *(float2*)((float*)C + (size_t)row * DIMc + col) = v0;
                *(float2*)((float*)C + (size_t)(row + 8) * DIMc + col) = v1;
            } else {
                __half2 p0 = __floats2half2_rn(acc[i][j][0], acc[i][j][1]);
                __half2 p1 = __floats2half2_rn(acc[i][j][2], acc[i][j][3]);
                *(__half2*)((__half*)C + (size_t)row * DIMc + col) = p0;
                *(__half2*)((__half*)C + (size_t)(row + 8) * DIMc + col) = p1;
            }
        }
    }

    // fused per-column sum(w^2) partials (GEMM1 only)
    if (sumsq) {
        __shared__ float ssq[2][128];
#pragma unroll
        for (int j = 0; j < 8; j++) {
            float s0 = 0.f, s1 = 0.f;
#pragma unroll
            for (int i = 0; i < 4; i++) {
                s0 += acc[i][j][0] * acc[i][j][0] + acc[i][j][2] * acc[i][j][2];
                s1 += acc[i][j][1] * acc[i][j][1] + acc[i][j][3] * acc[i][j][3];
            }
#pragma unroll
            for (int o = 4; o < 32; o <<= 1) {
                s0 += __shfl_xor_sync(0xffffffffu, s0, o);
                s1 += __shfl_xor_sync(0xffffffffu, s1, o);
            }
            if (lane < 4) {
                ssq[wm][wn * 64 + j * 8 + qc * 2]     = s0;
                ssq[wm][wn * 64 + j * 8 + qc * 2 + 1] = s1;
            }
        }
        __syncthreads();
        if (tid < 128) {
            int b  = bm >> 5;
            int sp = bm & 31;
            sumsq[(size_t)(sp * Bb + b) * DIMc + bn * 128 + tid]
                = ssq[0][tid] + ssq[1][tid];
        }
    }
}

// ====== merged fp32 -> fp16 conversion (x, Wqkv, Wout in one launch) ======
#define XBLK   ((Mm * (size_t)DIMc) / 2048)          // 16384
#define WBLK   ((DIMc * DIMc) / 2048)                // 512
__global__ void convert_all(const float* __restrict__ x, __half* __restrict__ xh,
                            const float* __restrict__ W1, __half* __restrict__ W1h,
                            const float* __restrict__ W2, __half* __restrict__ W2h) {
    size_t blk = blockIdx.x;
    const float* src; __half* dst;
    if (blk < XBLK) { src = x; dst = xh; }
    else if (blk < XBLK + WBLK) { src = W1; dst = W1h; blk -= XBLK; }
    else { src = W2; dst = W2h; blk -= XBLK + WBLK; }
    size_t i = (blk * 256 + threadIdx.x) * 8;
    float4 v0 = *(const float4*)(src + i);
    float4 v1 = *(const float4*)(src + i + 4);
    __half2 h[4];
    h[0] = __floats2half2_rn(v0.x, v0.y);
    h[1] = __floats2half2_rn(v0.z, v0.w);
    h[2] = __floats2half2_rn(v1.x, v1.y);
    h[3] = __floats2half2_rn(v1.z, v1.w);
    *(uint4*)(dst + i) = *(uint4*)h;
}

__global__ void reduce_innorm() {
    int idx = blockIdx.x * 256 + threadIdx.x;
    int b = idx >> 10, c = idx & 1023;
    float s = 0.f;
#pragma unroll
    for (int sp = 0; sp < NSPLIT; sp++) s += g_part1[(sp * Bb + b) * DIMc + c];
    g_innorm[idx] = 1.0f / fmaxf(s, 1e-24f);
}

// ------- logits + softmax over heads + fused dots partials (fp16 w) -------
__global__ void logits_softmax_dots(const float* __restrict__ temp) {
    int warp = threadIdx.x >> 5, lane = threadIdx.x & 31;
    int r = blockIdx.x * 8 + warp;
    int b = r >> 12;
    const __half* wrow = g_wh + (size_t)r * DIMc;
    const float* inn   = g_innorm + b * DIMc;

    float v0[16], v1[16], acc[16];
#pragma unroll
    for (int h = 0; h < 16; h++) {
        int c = h * 64 + lane * 2;
        float2 wv = __half22float2(*(const __half2*)(wrow + c));
        float2 in2 = *(const float2*)(inn + c);
        v0[h] = wv.x; v1[h] = wv.y;
        acc[h] = wv.x * wv.x * in2.x + wv.y * wv.y * in2.y;
    }
#pragma unroll
    for (int h = 0; h < 16; h++) {
        float s = acc[h];
#pragma unroll
        for (int o = 16; o; o >>= 1) s += __shfl_xor_sync(0xffffffffu, s, o);
        acc[h] = s * temp[h];
    }
    float mx = acc[0];
#pragma unroll
    for (int h = 1; h < 16; h++) mx = fmaxf(mx, acc[h]);
    float ssum = 0.f;
#pragma unroll
    for (int h = 0; h < 16; h++) { acc[h] = expf(acc[h] - mx); ssum += acc[h]; }
    float inv = 1.0f / ssum;
#pragma unroll
    for (int h = 0; h < 16; h++) acc[h] *= inv;      // acc = Pi

    __shared__ float sdots[8][DIMc];
    __shared__ float sPi[8][16];
    if (lane == 0) {
#pragma unroll
        for (int h = 0; h < 16; h++) {
            g_Pi[(size_t)r * Hh + h] = acc[h];
            sPi[warp][h] = acc[h];
        }
    }
#pragma unroll
    for (int h = 0; h < 16; h++) {
        int c = h * 64 + lane * 2;
        float2 d2 = make_float2(acc[h] * v0[h] * v0[h], acc[h] * v1[h] * v1[h]);
        *(float2*)(&sdots[warp][c]) = d2;
    }
    __syncthreads();
#pragma unroll
    for (int k = 0; k < 4; k++) {
        int c = threadIdx.x + k * 256;
        float s = 0.f;
#pragma unroll
        for (int w = 0; w < 8; w++) s += sdots[w][c];
        g_dpart[(size_t)blockIdx.x * DIMc + c] = s;
    }
    if (threadIdx.x < 16) {
        float s = 0.f;
#pragma unroll
        for (int w = 0; w < 8; w++) s += sPi[w][threadIdx.x];
        g_Sp[blockIdx.x * 16 + threadIdx.x] = s;
    }
}

__global__ void reduce_S() {
    int bh = blockIdx.x;
    int b = bh >> 4, h = bh & 15;
    __shared__ float sm[128];
    float s = 0.f;
    const int blocksPerBatch = (Nseq / 8);
    for (int i = threadIdx.x; i < blocksPerBatch; i += 128)
        s += g_Sp[(b * blocksPerBatch + i) * 16 + h];
    sm[threadIdx.x] = s;
    __syncthreads();
    for (int o = 64; o; o >>= 1) {
        if (threadIdx.x < o) sm[threadIdx.x] += sm[threadIdx.x + o];
        __syncthreads();
    }
    if (threadIdx.x == 0) g_invS[bh] = 1.0f / (sm[0] + 1e-8f);
}

__global__ void dots_gather() {
    int c   = blockIdx.x * 256 + threadIdx.x;
    int grp = blockIdx.y;
    int b   = blockIdx.z;
    const int bpb = Nseq / 8;
    float s = 0.f;
#pragma unroll
    for (int i = 0; i < 16; i++)
        s += g_dpart[(size_t)(b * bpb + grp * 16 + i) * DIMc + c];
    g_part2[(grp * Bb + b) * DIMc + c] = s;
}

__global__ void reduce_attn() {
    int idx = blockIdx.x * 256 + threadIdx.x;
    int b = idx >> 10, c = idx & 1023, h = c >> 6;
    float s = 0.f;
#pragma unroll
    for (int sp = 0; sp < NSPLIT; sp++) s += g_part2[(sp * Bb + b) * DIMc + c];
    float dots = s * g_invS[b * 16 + h];
    g_attn[idx] = 1.0f / (1.0f + dots);
}

// ---------------- y = fp16(-w * Pi * attn), fp16 w ------------------------
__global__ void y_pass() {
    size_t i4 = (size_t)blockIdx.x * 256 + threadIdx.x;
    size_t m  = i4 >> 8;
    int cb = (int)(i4 & 255) * 4;
    int b  = (int)(m >> 12);
    uint2 wp = *(const uint2*)(g_wh + m * DIMc + cb);
    float2 w0 = __half22float2(*(__half2*)&wp.x);
    float2 w1 = __half22float2(*(__half2*)&wp.y);
    float pi  = g_Pi[m * Hh + (cb >> 6)];
    float4 at = *(const float4*)(g_attn + (size_t)b * DIMc + cb);
    __half2 h0 = __floats2half2_rn(-w0.x * pi * at.x, -w0.y * pi * at.y);
    __half2 h1 = __floats2half2_rn(-w1.x * pi * at.z, -w1.y * pi * at.w);
    uint2 pk = make_uint2(*(uint32_t*)&h0, *(uint32_t*)&h1);
    *(uint2*)(g_yh + m * DIMc + cb) = pk;
}

// ---------------- launch ---------------------------------------------------
extern "C" void kernel_launch(void* const* d_in, const int* in_sizes, int n_in,
                              void* d_out, int out_size) {
    const float* x    = (const float*)d_in[0];
    const float* Wqkv = (const float*)d_in[1];
    const float* temp = (const float*)d_in[2];
    const float* Wout = (const float*)d_in[3];
    const float* bout = (const float*)d_in[4];
    float* out = (float*)d_out;

    cudaFuncSetAttribute(gemm_f16<__half>, cudaFuncAttributeMaxDynamicSharedMemorySize, GSMEM);
    cudaFuncSetAttribute(gemm_f16<float>,  cudaFuncAttributeMaxDynamicSharedMemorySize, GSMEM);
    cudaFuncSetAttribute(gemm_f16<__half>, cudaFuncAttributePreferredSharedMemoryCarveout, 100);
    cudaFuncSetAttribute(gemm_f16<float>,  cudaFuncAttributePreferredSharedMemoryCarveout, 100);

    __half* wh_ptr; cudaGetSymbolAddress((void**)&wh_ptr, g_wh);
    float*  p1_ptr; cudaGetSymbolAddress((void**)&p1_ptr, g_part1);
    __half* xh_ptr; cudaGetSymbolAddress((void**)&xh_ptr, g_xh);
    __half* yh_ptr; cudaGetSymbolAddress((void**)&yh_ptr, g_yh);
    __half* w1_ptr; cudaGetSymbolAddress((void**)&w1_ptr, g_W1h);
    __half* w2_ptr; cudaGetSymbolAddress((void**)&w2_ptr, g_W2h);

    convert_all<<<XBLK + 2 * WBLK, 256>>>(x, xh_ptr, Wqkv, w1_ptr, Wout, w2_ptr);

    dim3 gemmGrid(DIMc / 128, Mm / 128);               // (8, 256)
    gemm_f16<__half><<<gemmGrid, 128, GSMEM>>>(xh_ptr, w1_ptr, wh_ptr, nullptr, p1_ptr);

    reduce_innorm<<<(Bb * DIMc) / 256, 256>>>();
    logits_softmax_dots<<<Mm / 8, 256>>>(temp);
    reduce_S<<<Bb * Hh, 128>>>();
    dots_gather<<<dim3(DIMc / 256, NSPLIT, Bb), 256>>>();
    reduce_attn<<<(Bb * DIMc) / 256, 256>>>();
    y_pass<<<(Mm * (size_t)DIMc) / 1024, 256>>>();

    gemm_f16<float><<<gemmGrid, 128, GSMEM>>>(yh_ptr, w2_ptr, out, bout, nullptr);
}

// round 15
// speedup vs baseline: 1.6800x; 1.6800x over previous
#include <cuda_runtime.h>
#include <cuda_fp16.h>
#include <cstdint>

// Problem constants
#define Bb    8
#define Nseq  4096
#define DIMc  1024
#define Hh    16
#define Mm    (Bb * Nseq)      // 32768 rows
#define NSPLIT 32

// ---------------- scratch (static device allocations only) ----------------
__device__ __align__(16) __half g_wh[(size_t)Mm * DIMc];   // w in fp16 (64MB)
__device__ __align__(16) __half g_xh[(size_t)Mm * DIMc];
__device__ __align__(16) __half g_yh[(size_t)Mm * DIMc];
__device__ __align__(16) __half g_W1h[DIMc * DIMc];
__device__ __align__(16) __half g_W2h[DIMc * DIMc];
__device__ float g_Pi[Mm * Hh];
__device__ float g_part1[NSPLIT * Bb * DIMc];
__device__ float g_part2[NSPLIT * Bb * DIMc];
__device__ float g_innorm[Bb * DIMc];
__device__ float g_Sp[(Mm / 8) * Hh];
__device__ float g_invS[Bb * Hh];
__device__ float g_attn[Bb * DIMc];
__device__ float g_dpart[(size_t)(Mm / 8) * DIMc];

// ============================ helpers ======================================
#define CP16(dst, src) \
    asm volatile("cp.async.cg.shared.global [%0], [%1], 16;" :: "r"(dst), "l"(src) : "memory")
#define CP_COMMIT() asm volatile("cp.async.commit_group;" ::: "memory")
#define CP_WAIT(n)  asm volatile("cp.async.wait_group %0;" :: "n"(n) : "memory")

__device__ __forceinline__ uint32_t smem_u32(const void* p) {
    uint32_t a;
    asm("{ .reg .u64 t; cvta.to.shared.u64 t, %1; cvt.u32.u64 %0, t; }"
        : "=r"(a) : "l"(p));
    return a;
}
#define LDSM4(r0, r1, r2, r3, addr) \
    asm volatile("ldmatrix.sync.aligned.m8n8.x4.shared.b16 {%0,%1,%2,%3}, [%4];" \
        : "=r"(r0), "=r"(r1), "=r"(r2), "=r"(r3) : "r"(addr))

__device__ __forceinline__ void mma_f16(float c[4], uint32_t a0, uint32_t a1,
                                        uint32_t a2, uint32_t a3,
                                        uint32_t b0, uint32_t b1) {
    asm volatile(
        "mma.sync.aligned.m16n8k16.row.col.f32.f16.f16.f32 "
        "{%0,%1,%2,%3}, {%4,%5,%6,%7}, {%8,%9}, {%0,%1,%2,%3};"
        : "+f"(c[0]), "+f"(c[1]), "+f"(c[2]), "+f"(c[3])
        : "r"(a0), "r"(a1), "r"(a2), "r"(a3), "r"(b0), "r"(b1));
}

// ======================= fp16 GEMM (mma.sync m16n8k16) =====================
// Block tile 128x128, 128 threads = 4 warps (2M x 2N), warp tile 64x64.
// K chunked by 32, 4-stage cp.async pipeline. FROZEN config (R12 optimum).
#define KC      32
#define SROWH   40
#define STG_B   (128 * SROWH * 2 * 2)       // 20480 bytes per stage
#define NSTG    4
#define GSMEM   (NSTG * STG_B)              // 81920 bytes
#define AREG_B  (128 * SROWH * 2)

template <typename OutT>
__global__ __launch_bounds__(128, 2)
void gemm_f16(const __half* __restrict__ A, const __half* __restrict__ W,
              OutT* __restrict__ C, const float* __restrict__ bias,
              float* __restrict__ sumsq) {
    extern __shared__ __half smemh[];
    const int tid = threadIdx.x, wid = tid >> 5, lane = tid & 31;
    const int bn = blockIdx.x, bm = blockIdx.y;
    const int wm = wid & 1, wn = wid >> 1;
    const int q  = lane >> 2, qc = lane & 3;
    const uint32_t smb = smem_u32(smemh);

    uint32_t soff[8];
    const __half* gptr[8];
#pragma unroll
    for (int s = 0; s < 8; s++) {
        int seg = tid + s * 128;
        int isB = seg >> 9;
        int r = (seg & 511) >> 2, cseg = seg & 3;
        soff[s] = (uint32_t)(isB * AREG_B + (r * SROWH + cseg * 8) * 2);
        const __half* base = isB ? W + (size_t)(bn * 128 + r) * DIMc
                                 : A + (size_t)(bm * 128 + r) * DIMc;
        gptr[s] = base + cseg * 8;
    }
    auto load_chunk = [&](int c) {
        uint32_t st = smb + (uint32_t)((c & 3) * STG_B);
#pragma unroll
        for (int s = 0; s < 8; s++) CP16(st + soff[s], gptr[s] + c * KC);
        CP_COMMIT();
    };

    const int arow = (lane & 7) + 8 * ((lane >> 3) & 1);
    const int acol = 8 * (lane >> 4);
    const int brow = (lane & 7) + 8 * (lane >> 4);
    const int bcol = 8 * ((lane >> 3) & 1);

    float acc[4][8][4];
#pragma unroll
    for (int i = 0; i < 4; i++)
#pragma unroll
        for (int j = 0; j < 8; j++)
#pragma unroll
            for (int v = 0; v < 4; v++) acc[i][j][v] = 0.f;

    load_chunk(0); load_chunk(1); load_chunk(2);

    const int NCHUNK = DIMc / KC;        // 32
    for (int c = 0; c < NCHUNK; ++c) {
        CP_WAIT(2);
        __syncthreads();
        if (c + 3 < NCHUNK) load_chunk(c + 3);
        else CP_COMMIT();                // keep group count uniform

        uint32_t stA = smb + (uint32_t)((c & 3) * STG_B);
        uint32_t stB = stA + AREG_B;
#pragma unroll
        for (int ks = 0; ks < 2; ++ks) {
            const int k0 = ks * 16;
            uint32_t af[4][4], bf[8][2];
#pragma unroll
            for (int i = 0; i < 4; i++) {
                uint32_t ad = stA + (uint32_t)(((wm * 64 + i * 16 + arow) * SROWH
                                                + k0 + acol) * 2);
                LDSM4(af[i][0], af[i][1], af[i][2], af[i][3], ad);
            }
#pragma unroll
            for (int jp = 0; jp < 4; jp++) {
                uint32_t bd = stB + (uint32_t)(((wn * 64 + jp * 16 + brow) * SROWH
                                                + k0 + bcol) * 2);
                uint32_t t0, t1, t2, t3;
                LDSM4(t0, t1, t2, t3, bd);
                bf[jp * 2][0] = t0; bf[jp * 2][1] = t1;
                bf[jp * 2 + 1][0] = t2; bf[jp * 2 + 1][1] = t3;
            }
#pragma unroll
            for (int i = 0; i < 4; i++)
#pragma unroll
                for (int j = 0; j < 8; j++)
                    mma_f16(acc[i][j], af[i][0], af[i][1], af[i][2], af[i][3],
                            bf[j][0], bf[j][1]);
        }
    }

    // epilogue
#pragma unroll
    for (int j = 0; j < 8; j++) {
        int col = bn * 128 + wn * 64 + j * 8 + qc * 2;
        float b0 = 0.f, b1 = 0.f;
        if (bias) { b0 = bias[col]; b1 = bias[col + 1]; }
#pragma unroll
        for (int i = 0; i < 4; i++) {
            int row = bm * 128 + wm * 64 + i * 16 + q;
            if constexpr (sizeof(OutT) == 4) {
                float2 v0 = make_float2(acc[i][j][0] + b0, acc[i][j][1] + b1);
                float2 v1 = make_float2(acc[i][j][2] + b0, acc[i][j][3] + b1);
                *(float2*)((float*)C + (size_t)row * DIMc + col) = v0;
                *(float2*)((float*)C + (size_t)(row + 8) * DIMc + col) = v1;
            } else {
                __half2 p0 = __floats2half2_rn(acc[i][j][0], acc[i][j][1]);
                __half2 p1 = __floats2half2_rn(acc[i][j][2], acc[i][j][3]);
                *(__half2*)((__half*)C + (size_t)row * DIMc + col) = p0;
                *(__half2*)((__half*)C + (size_t)(row + 8) * DIMc + col) = p1;
            }
        }
    }

    // fused per-column sum(w^2) partials (GEMM1 only)
    if (sumsq) {
        __shared__ float ssq[2][128];
#pragma unroll
        for (int j = 0; j < 8; j++) {
            float s0 = 0.f, s1 = 0.f;
#pragma unroll
            for (int i = 0; i < 4; i++) {
                s0 += acc[i][j][0] * acc[i][j][0] + acc[i][j][2] * acc[i][j][2];
                s1 += acc[i][j][1] * acc[i][j][1] + acc[i][j][3] * acc[i][j][3];
            }
#pragma unroll
            for (int o = 4; o < 32; o <<= 1) {
                s0 += __shfl_xor_sync(0xffffffffu, s0, o);
                s1 += __shfl_xor_sync(0xffffffffu, s1, o);
            }
            if (lane < 4) {
                ssq[wm][wn * 64 + j * 8 + qc * 2]     = s0;
                ssq[wm][wn * 64 + j * 8 + qc * 2 + 1] = s1;
            }
        }
        __syncthreads();
        if (tid < 128) {
            int b  = bm >> 5;
            int sp = bm & 31;
            sumsq[(size_t)(sp * Bb + b) * DIMc + bn * 128 + tid]
                = ssq[0][tid] + ssq[1][tid];
        }
    }
}

// ====== merged fp32 -> fp16 conversion (x, Wqkv, Wout in one launch) ======
#define XBLK   ((Mm * (size_t)DIMc) / 2048)          // 16384
#define WBLK   ((DIMc * DIMc) / 2048)                // 512
__global__ void convert_all(const float* __restrict__ x, __half* __restrict__ xh,
                            const float* __restrict__ W1, __half* __restrict__ W1h,
                            const float* __restrict__ W2, __half* __restrict__ W2h) {
    size_t blk = blockIdx.x;
    const float* src; __half* dst;
    if (blk < XBLK) { src = x; dst = xh; }
    else if (blk < XBLK + WBLK) { src = W1; dst = W1h; blk -= XBLK; }
    else { src = W2; dst = W2h; blk -= XBLK + WBLK; }
    size_t i = (blk * 256 + threadIdx.x) * 8;
    float4 v0 = *(const float4*)(src + i);
    float4 v1 = *(const float4*)(src + i + 4);
    __half2 h[4];
    h[0] = __floats2half2_rn(v0.x, v0.y);
    h[1] = __floats2half2_rn(v0.z, v0.w);
    h[2] = __floats2half2_rn(v1.x, v1.y);
    h[3] = __floats2half2_rn(v1.z, v1.w);
    *(uint4*)(dst + i) = *(uint4*)h;
}

__global__ void reduce_innorm() {
    int idx = blockIdx.x * 256 + threadIdx.x;
    int b = idx >> 10, c = idx & 1023;
    float s = 0.f;
#pragma unroll
    for (int sp = 0; sp < NSPLIT; sp++) s += g_part1[(sp * Bb + b) * DIMc + c];
    g_innorm[idx] = 1.0f / fmaxf(s, 1e-24f);
}

// ------- logits + softmax over heads + fused dots partials (fp16 w) -------
__global__ void logits_softmax_dots(const float* __restrict__ temp) {
    int warp = threadIdx.x >> 5, lane = threadIdx.x & 31;
    int r = blockIdx.x * 8 + warp;
    int b = r >> 12;
    const __half* wrow = g_wh + (size_t)r * DIMc;
    const float* inn   = g_innorm + b * DIMc;

    float v0[16], v1[16], acc[16];
#pragma unroll
    for (int h = 0; h < 16; h++) {
        int c = h * 64 + lane * 2;
        float2 wv = __half22float2(*(const __half2*)(wrow + c));
        float2 in2 = *(const float2*)(inn + c);
        v0[h] = wv.x; v1[h] = wv.y;
        acc[h] = wv.x * wv.x * in2.x + wv.y * wv.y * in2.y;
    }
#pragma unroll
    for (int h = 0; h < 16; h++) {
        float s = acc[h];
#pragma unroll
        for (int o = 16; o; o >>= 1) s += __shfl_xor_sync(0xffffffffu, s, o);
        acc[h] = s * temp[h];
    }
    float mx = acc[0];
#pragma unroll
    for (int h = 1; h < 16; h++) mx = fmaxf(mx, acc[h]);
    float ssum = 0.f;
#pragma unroll
    for (int h = 0; h < 16; h++) { acc[h] = expf(acc[h] - mx); ssum += acc[h]; }
    float inv = 1.0f / ssum;
#pragma unroll
    for (int h = 0; h < 16; h++) acc[h] *= inv;      // acc = Pi

    __shared__ float sdots[8][DIMc];
    __shared__ float sPi[8][16];
    if (lane == 0) {
#pragma unroll
        for (int h = 0; h < 16; h++) {
            g_Pi[(size_t)r * Hh + h] = acc[h];
            sPi[warp][h] = acc[h];
        }
    }
#pragma unroll
    for (int h = 0; h < 16; h++) {
        int c = h * 64 + lane * 2;
        float2 d2 = make_float2(acc[h] * v0[h] * v0[h], acc[h] * v1[h] * v1[h]);
        *(float2*)(&sdots[warp][c]) = d2;
    }
    __syncthreads();
#pragma unroll
    for (int k = 0; k < 4; k++) {
        int c = threadIdx.x + k * 256;
        float s = 0.f;
#pragma unroll
        for (int w = 0; w < 8; w++) s += sdots[w][c];
        g_dpart[(size_t)blockIdx.x * DIMc + c] = s;
    }
    if (threadIdx.x < 16) {
        float s = 0.f;
#pragma unroll
        for (int w = 0; w < 8; w++) s += sPi[w][threadIdx.x];
        g_Sp[blockIdx.x * 16 + threadIdx.x] = s;
    }
}

__global__ void reduce_S() {
    int bh = blockIdx.x;
    int b = bh >> 4, h = bh & 15;
    __shared__ float sm[128];
    float s = 0.f;
    const int blocksPerBatch = (Nseq / 8);
    for (int i = threadIdx.x; i < blocksPerBatch; i += 128)
        s += g_Sp[(b * blocksPerBatch + i) * 16 + h];
    sm[threadIdx.x] = s;
    __syncthreads();
    for (int o = 64; o; o >>= 1) {
        if (threadIdx.x < o) sm[threadIdx.x] += sm[threadIdx.x + o];
        __syncthreads();
    }
    if (threadIdx.x == 0) g_invS[bh] = 1.0f / (sm[0] + 1e-8f);
}

__global__ void dots_gather() {
    int c   = blockIdx.x * 256 + threadIdx.x;
    int grp = blockIdx.y;
    int b   = blockIdx.z;
    const int bpb = Nseq / 8;
    float s = 0.f;
#pragma unroll
    for (int i = 0; i < 16; i++)
        s += g_dpart[(size_t)(b * bpb + grp * 16 + i) * DIMc + c];
    g_part2[(grp * Bb + b) * DIMc + c] = s;
}

__global__ void reduce_attn() {
    int idx = blockIdx.x * 256 + threadIdx.x;
    int b = idx >> 10, c = idx & 1023, h = c >> 6;
    float s = 0.f;
#pragma unroll
    for (int sp = 0; sp < NSPLIT; sp++) s += g_part2[(sp * Bb + b) * DIMc + c];
    float dots = s * g_invS[b * 16 + h];
    g_attn[idx] = 1.0f / (1.0f + dots);
}

// ---------------- y = fp16(-w * Pi * attn), fp16 w ------------------------
__global__ void y_pass() {
    size_t i4 = (size_t)blockIdx.x * 256 + threadIdx.x;
    size_t m  = i4 >> 8;
    int cb = (int)(i4 & 255) * 4;
    int b  = (int)(m >> 12);
    uint2 wp = *(const uint2*)(g_wh + m * DIMc + cb);
    float2 w0 = __half22float2(*(__half2*)&wp.x);
    float2 w1 = __half22float2(*(__half2*)&wp.y);
    float pi  = g_Pi[m * Hh + (cb >> 6)];
    float4 at = *(const float4*)(g_attn + (size_t)b * DIMc + cb);
    __half2 h0 = __floats2half2_rn(-w0.x * pi * at.x, -w0.y * pi * at.y);
    __half2 h1 = __floats2half2_rn(-w1.x * pi * at.z, -w1.y * pi * at.w);
    uint2 pk = make_uint2(*(uint32_t*)&h0, *(uint32_t*)&h1);
    *(uint2*)(g_yh + m * DIMc + cb) = pk;
}

// ---------------- launch ---------------------------------------------------
extern "C" void kernel_launch(void* const* d_in, const int* in_sizes, int n_in,
                              void* d_out, int out_size) {
    const float* x    = (const float*)d_in[0];
    const float* Wqkv = (const float*)d_in[1];
    const float* temp = (const float*)d_in[2];
    const float* Wout = (const float*)d_in[3];
    const float* bout = (const float*)d_in[4];
    float* out = (float*)d_out;

    cudaFuncSetAttribute(gemm_f16<__half>, cudaFuncAttributeMaxDynamicSharedMemorySize, GSMEM);
    cudaFuncSetAttribute(gemm_f16<float>,  cudaFuncAttributeMaxDynamicSharedMemorySize, GSMEM);

    __half* wh_ptr; cudaGetSymbolAddress((void**)&wh_ptr, g_wh);
    float*  p1_ptr; cudaGetSymbolAddress((void**)&p1_ptr, g_part1);
    __half* xh_ptr; cudaGetSymbolAddress((void**)&xh_ptr, g_xh);
    __half* yh_ptr; cudaGetSymbolAddress((void**)&yh_ptr, g_yh);
    __half* w1_ptr; cudaGetSymbolAddress((void**)&w1_ptr, g_W1h);
    __half* w2_ptr; cudaGetSymbolAddress((void**)&w2_ptr, g_W2h);

    convert_all<<<XBLK + 2 * WBLK, 256>>>(x, xh_ptr, Wqkv, w1_ptr, Wout, w2_ptr);

    dim3 gemmGrid(DIMc / 128, Mm / 128);               // (8, 256)
    gemm_f16<__half><<<gemmGrid, 128, GSMEM>>>(xh_ptr, w1_ptr, wh_ptr, nullptr, p1_ptr);

    reduce_innorm<<<(Bb * DIMc) / 256, 256>>>();
    logits_softmax_dots<<<Mm / 8, 256>>>(temp);
    reduce_S<<<Bb * Hh, 128>>>();
    dots_gather<<<dim3(DIMc / 256, NSPLIT, Bb), 256>>>();
    reduce_attn<<<(Bb * DIMc) / 256, 256>>>();
    y_pass<<<(Mm * (size_t)DIMc) / 1024, 256>>>();

    gemm_f16<float><<<gemmGrid, 128, GSMEM>>>(yh_ptr, w2_ptr, out, bout, nullptr);
}